// round 2
// baseline (speedup 1.0000x reference)
#include <cuda_runtime.h>
#include <math.h>

#define NB 4096
#define NC 1000
#define ND 2048

#define TAU   6.0f
#define ALPHA 1.0f
#define BETA  5.0f
#define LR    0.1f
#define PI_F  3.14159265358979f
#define EPS_F 1e-8f
#define DECAY 0.999f   /* 1 - LR*WD */

// ---- scratch state (device globals: no allocation allowed) ----
__device__ float g_m[NB * NC];
__device__ float g_v[NB * NC];
__device__ float g_lse[NB];     // lse of current u, per row
__device__ float g_uy[NB];      // u[i, y_i]
__device__ float g_ltrg[NB];    // constant target per row
__device__ float g_ptrg[NB];    // constant per row
__device__ int   g_y[NB];       // argmax of z per row (constant)
__device__ float g_pmax[2][NB]; // per-row max softmax prob (double-buffered)
__device__ int   g_jmax[2][NB]; // per-row argmax col (double-buffered)

// =====================================================================
// GEMM: z = x @ W + b   (fp32, 128x64 tile, BK=16, 256 threads, 8x4/thr)
// =====================================================================
#define BM 128
#define BN 64
#define BK 16

__global__ __launch_bounds__(256) void sgemm_bias(
    const float* __restrict__ A,   // [NB, ND]
    const float* __restrict__ B,   // [ND, NC]
    const float* __restrict__ bias,// [NC]
    float* __restrict__ C)         // [NB, NC]
{
    __shared__ float As[BK][BM];   // transposed A tile
    __shared__ float Bs[BK][BN];

    const int tid = threadIdx.x;
    const int tx = tid & 15;       // 16 col-groups of 4
    const int ty = tid >> 4;       // 16 row-groups of 8
    const int rowBase = blockIdx.y * BM;
    const int colBase = blockIdx.x * BN;

    float acc[8][4];
#pragma unroll
    for (int q = 0; q < 8; q++)
#pragma unroll
        for (int w = 0; w < 4; w++) acc[q][w] = 0.0f;

    for (int k0 = 0; k0 < ND; k0 += BK) {
        // A tile: 128 rows x 16 k = 512 float4; 2 per thread, coalesced
#pragma unroll
        for (int i = 0; i < 2; i++) {
            int id = tid + i * 256;
            int r  = id >> 2;
            int kc = (id & 3) << 2;
            float4 av = *reinterpret_cast<const float4*>(
                &A[(size_t)(rowBase + r) * ND + k0 + kc]);
            As[kc + 0][r] = av.x;
            As[kc + 1][r] = av.y;
            As[kc + 2][r] = av.z;
            As[kc + 3][r] = av.w;
        }
        // B tile: 16 k-rows x 64 cols = 256 float4; 1 per thread
        {
            int r  = tid >> 4;
            int c  = (tid & 15) << 2;
            int gc = colBase + c;
            float4 bv = make_float4(0.f, 0.f, 0.f, 0.f);
            if (gc < NC)
                bv = *reinterpret_cast<const float4*>(&B[(size_t)(k0 + r) * NC + gc]);
            *reinterpret_cast<float4*>(&Bs[r][c]) = bv;
        }
        __syncthreads();

#pragma unroll
        for (int kk = 0; kk < BK; kk++) {
            float a[8];
#pragma unroll
            for (int q = 0; q < 8; q++) a[q] = As[kk][ty * 8 + q];
            float4 b4 = *reinterpret_cast<float4*>(&Bs[kk][tx * 4]);
            float bb[4] = {b4.x, b4.y, b4.z, b4.w};
#pragma unroll
            for (int q = 0; q < 8; q++)
#pragma unroll
                for (int w = 0; w < 4; w++)
                    acc[q][w] = fmaf(a[q], bb[w], acc[q][w]);
        }
        __syncthreads();
    }

#pragma unroll
    for (int q = 0; q < 8; q++) {
        int r = rowBase + ty * 8 + q;
#pragma unroll
        for (int w = 0; w < 4; w++) {
            int c = colBase + tx * 4 + w;
            if (c < NC) C[(size_t)r * NC + c] = acc[q][w] + bias[c];
        }
    }
}

// =====================================================================
// Init row stats from z: y, l_trg, p_trg, lse, u[y], pmax/jmax (parity 1)
// =====================================================================
__global__ __launch_bounds__(256) void init_stats(const float* __restrict__ U)
{
    int gw   = (blockIdx.x * blockDim.x + threadIdx.x) >> 5;
    int lane = threadIdx.x & 31;
    if (gw >= NB) return;
    const float* row = U + (size_t)gw * NC;

    // pass 1: max + first-argmax
    float bv = -INFINITY; int bj = NC;
    for (int j = lane; j < NC; j += 32) {
        float v = row[j];
        if (v > bv) { bv = v; bj = j; }   // ascending j -> first on tie
    }
#pragma unroll
    for (int off = 16; off; off >>= 1) {
        float ov = __shfl_down_sync(0xffffffffu, bv, off);
        int   oj = __shfl_down_sync(0xffffffffu, bj, off);
        if (ov > bv || (ov == bv && oj < bj)) { bv = ov; bj = oj; }
    }
    bv = __shfl_sync(0xffffffffu, bv, 0);
    bj = __shfl_sync(0xffffffffu, bj, 0);

    // pass 2: sumexp
    float se = 0.0f;
    for (int j = lane; j < NC; j += 32) se += expf(row[j] - bv);
#pragma unroll
    for (int off = 16; off; off >>= 1) se += __shfl_xor_sync(0xffffffffu, se, off);

    if (lane == 0) {
        float l_org = logf(se);                 // lse - z[y] since z[y]=rowmax
        float l_atr = (floorf(l_org / TAU) + 0.5f) * TAU;
        float l_trg = l_org - ALPHA * TAU *
                      sinf(PI_F * (1.0f - 2.0f * (l_org - l_atr) / TAU));
        float pm = 1.0f / se;                   // max softmax prob of the row
        g_y[gw]    = bj;
        g_ltrg[gw] = l_trg;
        g_ptrg[gw] = pm;
        g_lse[gw]  = bv + l_org;
        g_uy[gw]   = bv;
        g_pmax[1][gw] = pm;
        g_jmax[1][gw] = bj;
    }
}

// =====================================================================
// One AdamW step, fully fused. 512 blocks x 256 thr; warp-per-row (8/block).
// Phase A (per block, redundant): scalars M, i*, j*, S from parity pr.
// Phase B: per-row gradient + AdamW update; new row stats -> parity pr^1.
// =====================================================================
__global__ __launch_bounds__(256) void fused_step(
    float* __restrict__ U, int pr, float bc1, float bc2, int first)
{
    __shared__ float sV[256];
    __shared__ int   sI[256];
    __shared__ float sS[256];

    const int tid = threadIdx.x;

    // --- Phase A: global max of pmax + argrow ---
    float bv = -INFINITY; int bi = NB;
    for (int r = tid; r < NB; r += 256) {
        float v = g_pmax[pr][r];
        if (v > bv) { bv = v; bi = r; }     // ascending r -> first on tie
    }
    sV[tid] = bv; sI[tid] = bi;
    __syncthreads();
#pragma unroll
    for (int off = 128; off; off >>= 1) {
        if (tid < off) {
            float ov = sV[tid + off]; int oi = sI[tid + off];
            if (ov > sV[tid] || (ov == sV[tid] && oi < sI[tid])) {
                sV[tid] = ov; sI[tid] = oi;
            }
        }
        __syncthreads();
    }
    const float M    = sV[0];
    const int   istar = sI[0];

    // --- S = sum sign(M - p_trg) ---
    float ps = 0.0f;
    for (int r = tid; r < NB; r += 256) {
        float d = M - g_ptrg[r];
        ps += (d > 0.0f) ? 1.0f : ((d < 0.0f) ? -1.0f : 0.0f);
    }
    sS[tid] = ps;
    __syncthreads();
#pragma unroll
    for (int off = 128; off; off >>= 1) {
        if (tid < off) sS[tid] += sS[tid + off];
        __syncthreads();
    }
    const float S = sS[0];
    const int jstar = g_jmax[pr][istar];

    // --- Phase B: row update ---
    const int lane = tid & 31;
    const int w    = tid >> 5;
    const int i    = blockIdx.x * 8 + w;

    const float lse  = g_lse[i];
    const float uyv  = g_uy[i];
    const int   y    = g_y[i];
    const float d1   = (lse - uyv) - g_ltrg[i];
    const float sign1 = (d1 > 0.0f) ? 1.0f : ((d1 < 0.0f) ? -1.0f : 0.0f);
    const bool  isStar = (i == istar);
    const float c2 = BETA * S * M;

    float* Urow = U   + (size_t)i * NC;
    float* mrow = g_m + (size_t)i * NC;
    float* vrow = g_v + (size_t)i * NC;

    float un[32];
    float bvn = -INFINITY; int bjn = NC;
    float uyNew = 0.0f;

#pragma unroll
    for (int k = 0; k < 32; k++) {
        int j = k * 32 + lane;
        if (j < NC) {
            float u = Urow[j];
            float s = expf(u - lse);
            float g = sign1 * (s - ((j == y) ? 1.0f : 0.0f));
            if (isStar) g += c2 * (((j == jstar) ? 1.0f : 0.0f) - s);
            float m, v;
            if (first) { m = 0.1f * g;               v = 0.001f * g * g; }
            else       { m = 0.9f * mrow[j] + 0.1f * g;
                         v = 0.999f * vrow[j] + 0.001f * g * g; }
            mrow[j] = m; vrow[j] = v;
            float upd  = (m * bc1) / (sqrtf(v * bc2) + EPS_F);
            float unew = u * DECAY - LR * upd;
            Urow[j] = unew;
            un[k] = unew;
            if (unew > bvn) { bvn = unew; bjn = j; }
            if (j == y) uyNew = unew;
        } else {
            un[k] = -INFINITY;
        }
    }

    // warp reduce: rowmax + first-argmax of new u
#pragma unroll
    for (int off = 16; off; off >>= 1) {
        float ov = __shfl_down_sync(0xffffffffu, bvn, off);
        int   oj = __shfl_down_sync(0xffffffffu, bjn, off);
        if (ov > bvn || (ov == bvn && oj < bjn)) { bvn = ov; bjn = oj; }
    }
    bvn = __shfl_sync(0xffffffffu, bvn, 0);
    bjn = __shfl_sync(0xffffffffu, bjn, 0);

    // sumexp of new u from registers
    float se = 0.0f;
#pragma unroll
    for (int k = 0; k < 32; k++) {
        int j = k * 32 + lane;
        if (j < NC) se += expf(un[k] - bvn);
    }
#pragma unroll
    for (int off = 16; off; off >>= 1) se += __shfl_xor_sync(0xffffffffu, se, off);

    uyNew = __shfl_sync(0xffffffffu, uyNew, y & 31);

    if (lane == 0) {
        g_lse[i] = bvn + logf(se);
        g_uy[i]  = uyNew;
        g_pmax[pr ^ 1][i] = 1.0f / se;
        g_jmax[pr ^ 1][i] = bjn;
    }
}

// =====================================================================
extern "C" void kernel_launch(void* const* d_in, const int* in_sizes, int n_in,
                              void* d_out, int out_size)
{
    const float* x = (const float*)d_in[0];   // [4096, 2048]
    const float* W = (const float*)d_in[1];   // [2048, 1000]
    const float* b = (const float*)d_in[2];   // [1000]
    float* U = (float*)d_out;                 // [4096, 1000]

    dim3 ggrid((NC + BN - 1) / BN, NB / BM);  // (16, 32)
    sgemm_bias<<<ggrid, 256>>>(x, W, b, U);

    init_stats<<<NB / 8, 256>>>(U);           // 512 blocks, warp per row

    for (int t = 1; t <= 100; t++) {
        float bc1 = (float)(1.0 / (1.0 - pow(0.9,   (double)t)));
        float bc2 = (float)(1.0 / (1.0 - pow(0.999, (double)t)));
        fused_step<<<NB / 8, 256>>>(U, t & 1, bc1, bc2, (t == 1) ? 1 : 0);
    }
}

// round 3
// speedup vs baseline: 1.1393x; 1.1393x over previous
#include <cuda_runtime.h>
#include <math.h>

#define NB 4096
#define NC 1000
#define ND 2048

#define TAU   6.0f
#define ALPHA 1.0f
#define BETA  5.0f
#define LR    0.1f
#define PI_F  3.14159265358979f
#define EPS_F 1e-8f
#define DECAY 0.999f   /* 1 - LR*WD */

// ---- scratch state (device globals: no allocation allowed) ----
__device__ float g_m[NB * NC];
__device__ float g_v[NB * NC];
__device__ float g_ptrg[NB];    // constant per row (needed cross-block)
__device__ float g_pmax[2][NB]; // per-row max softmax prob (double-buffered)
__device__ int   g_jmax[2][NB]; // per-row argmax col (double-buffered)
__device__ int           g_bar_count;
__device__ volatile int  g_bar_gen;

// =====================================================================
// GEMM: z = x @ W + b. 128x128 tile, BK=16, 256 thr, 8x8/thr, double-buf.
// Per-output fmaf chain is k-sequential 0..2047 -> bitwise identical to R1.
// =====================================================================
#define GBK 16

__global__ __launch_bounds__(256) void sgemm_bias(
    const float* __restrict__ A,   // [NB, ND]
    const float* __restrict__ B,   // [ND, NC]
    const float* __restrict__ bias,// [NC]
    float* __restrict__ C)         // [NB, NC]
{
    __shared__ float As[2][GBK][128];
    __shared__ float Bs[2][GBK][128];

    const int tid = threadIdx.x;
    const int tx = tid & 15;       // 16 col-groups of 8
    const int ty = tid >> 4;       // 16 row-groups of 8
    const int rowBase = blockIdx.y * 128;
    const int colBase = blockIdx.x * 128;

    float acc[8][8];
#pragma unroll
    for (int q = 0; q < 8; q++)
#pragma unroll
        for (int p = 0; p < 8; p++) acc[q][p] = 0.0f;

    // loader coords (2 float4 each for A and B per thread)
    // A: id in [0,512): r=id>>2, kc=(id&3)<<2  (128 rows x 16 k)
    // B: id in [0,512): kr=id>>5, cc=(id&31)<<2 (16 k-rows x 128 cols)

    // prologue: tile 0 straight to smem[0]
#pragma unroll
    for (int h = 0; h < 2; h++) {
        int id = tid + h * 256;
        int r  = id >> 2;
        int kc = (id & 3) << 2;
        float4 av = *reinterpret_cast<const float4*>(
            &A[(size_t)(rowBase + r) * ND + kc]);
        As[0][kc + 0][r] = av.x;
        As[0][kc + 1][r] = av.y;
        As[0][kc + 2][r] = av.z;
        As[0][kc + 3][r] = av.w;

        int kr = id >> 5;
        int cc = (id & 31) << 2;
        int gc = colBase + cc;
        float4 bv = make_float4(0.f, 0.f, 0.f, 0.f);
        if (gc < NC)
            bv = *reinterpret_cast<const float4*>(&B[(size_t)kr * NC + gc]);
        *reinterpret_cast<float4*>(&Bs[0][kr][cc]) = bv;
    }
    __syncthreads();

    int buf = 0;
    for (int kt = 0; kt < ND / GBK; kt++) {
        float4 pa[2], pb[2];
        const bool hasNext = (kt + 1 < ND / GBK);
        if (hasNext) {
            int k0 = (kt + 1) * GBK;
#pragma unroll
            for (int h = 0; h < 2; h++) {
                int id = tid + h * 256;
                int r  = id >> 2;
                int kc = (id & 3) << 2;
                pa[h] = *reinterpret_cast<const float4*>(
                    &A[(size_t)(rowBase + r) * ND + k0 + kc]);
                int kr = id >> 5;
                int cc = (id & 31) << 2;
                int gc = colBase + cc;
                pb[h] = make_float4(0.f, 0.f, 0.f, 0.f);
                if (gc < NC)
                    pb[h] = *reinterpret_cast<const float4*>(
                        &B[(size_t)(k0 + kr) * NC + gc]);
            }
        }

#pragma unroll
        for (int kk = 0; kk < GBK; kk++) {
            float a[8], bb[8];
#pragma unroll
            for (int q = 0; q < 8; q++) a[q]  = As[buf][kk][ty * 8 + q];
#pragma unroll
            for (int p = 0; p < 8; p++) bb[p] = Bs[buf][kk][tx * 8 + p];
#pragma unroll
            for (int q = 0; q < 8; q++)
#pragma unroll
                for (int p = 0; p < 8; p++)
                    acc[q][p] = fmaf(a[q], bb[p], acc[q][p]);
        }

        if (hasNext) {
            int nb = buf ^ 1;
#pragma unroll
            for (int h = 0; h < 2; h++) {
                int id = tid + h * 256;
                int r  = id >> 2;
                int kc = (id & 3) << 2;
                As[nb][kc + 0][r] = pa[h].x;
                As[nb][kc + 1][r] = pa[h].y;
                As[nb][kc + 2][r] = pa[h].z;
                As[nb][kc + 3][r] = pa[h].w;
                int kr = id >> 5;
                int cc = (id & 31) << 2;
                *reinterpret_cast<float4*>(&Bs[nb][kr][cc]) = pb[h];
            }
            __syncthreads();
            buf = nb;
        }
    }

#pragma unroll
    for (int q = 0; q < 8; q++) {
        int r = rowBase + ty * 8 + q;
#pragma unroll
        for (int p = 0; p < 8; p++) {
            int c = colBase + tx * 8 + p;
            if (c < NC) C[(size_t)r * NC + c] = acc[q][p] + bias[c];
        }
    }
}

// =====================================================================
// software grid barrier (all blocks co-resident: 1024 blocks, 7/SM cap)
// =====================================================================
__device__ __forceinline__ void grid_barrier(int nblocks)
{
    __syncthreads();
    __threadfence();
    if (threadIdx.x == 0) {
        int gen = g_bar_gen;
        if (atomicAdd(&g_bar_count, 1) == nblocks - 1) {
            g_bar_count = 0;
            __threadfence();
            g_bar_gen = gen + 1;
        } else {
            while (g_bar_gen == gen) { __nanosleep(64); }
        }
    }
    __syncthreads();
    __threadfence();
}

// =====================================================================
// Persistent kernel: init stats + all 100 AdamW steps. Warp-per-row,
// u held in registers the whole time; m,v in gmem (L2-resident).
// 1024 blocks x 128 threads (4 rows/block).
// =====================================================================
__global__ __launch_bounds__(128, 7) void persist_steps(float* __restrict__ U)
{
    __shared__ float sV[128];
    __shared__ int   sI[128];
    __shared__ float sS[128];
    __shared__ float sBC[2];

    const int tid  = threadIdx.x;
    const int lane = tid & 31;
    const int w    = tid >> 5;
    const int i    = blockIdx.x * 4 + w;
    const int nblocks = gridDim.x;

    float* Urow = U   + (size_t)i * NC;
    float* mrow = g_m + (size_t)i * NC;
    float* vrow = g_v + (size_t)i * NC;

    // ---- load row into registers ----
    float u[32];
#pragma unroll
    for (int k = 0; k < 32; k++) {
        int j = k * 32 + lane;
        u[k] = (j < NC) ? Urow[j] : -INFINITY;
    }

    // ---- init stats (identical arithmetic to R1 init_stats) ----
    float bv = -INFINITY; int bj = NC;
#pragma unroll
    for (int k = 0; k < 32; k++) {
        int j = k * 32 + lane;
        if (j < NC) { if (u[k] > bv) { bv = u[k]; bj = j; } }
    }
#pragma unroll
    for (int off = 16; off; off >>= 1) {
        float ov = __shfl_down_sync(0xffffffffu, bv, off);
        int   oj = __shfl_down_sync(0xffffffffu, bj, off);
        if (ov > bv || (ov == bv && oj < bj)) { bv = ov; bj = oj; }
    }
    bv = __shfl_sync(0xffffffffu, bv, 0);
    bj = __shfl_sync(0xffffffffu, bj, 0);

    float se = 0.0f;
#pragma unroll
    for (int k = 0; k < 32; k++) {
        int j = k * 32 + lane;
        if (j < NC) se += expf(u[k] - bv);
    }
#pragma unroll
    for (int off = 16; off; off >>= 1) se += __shfl_xor_sync(0xffffffffu, se, off);

    float l_org = logf(se);
    float l_atr = (floorf(l_org / TAU) + 0.5f) * TAU;
    const float ltrg = l_org - ALPHA * TAU *
                       sinf(PI_F * (1.0f - 2.0f * (l_org - l_atr) / TAU));
    float pm  = 1.0f / se;
    float lse = bv + l_org;     // lane-uniform
    float uy  = bv;             // z[i, y] = rowmax
    const int y = bj;

    if (lane == 0) {
        g_ptrg[i]     = pm;
        g_pmax[1][i]  = pm;
        g_jmax[1][i]  = bj;
    }

    // thread 0 keeps the bias-correction running products (double)
    double p1 = 1.0, p2 = 1.0;

    for (int t = 1; t <= 100; t++) {
        const int pr = t & 1;

        grid_barrier(nblocks);   // pmax/jmax/ptrg writes visible everywhere

        if (tid == 0) {
            p1 *= 0.9; p2 *= 0.999;
            sBC[0] = (float)(1.0 / (1.0 - p1));
            sBC[1] = (float)(1.0 / (1.0 - p2));
        }

        // --- Phase A: global max(pmax)+argrow (order-independent) ---
        float mbv = -INFINITY; int mbi = NB;
        for (int r = tid; r < NB; r += 128) {
            float pv = g_pmax[pr][r];
            if (pv > mbv) { mbv = pv; mbi = r; }
        }
        sV[tid] = mbv; sI[tid] = mbi;
        __syncthreads();
#pragma unroll
        for (int off = 64; off; off >>= 1) {
            if (tid < off) {
                float ov = sV[tid + off]; int oi = sI[tid + off];
                if (ov > sV[tid] || (ov == sV[tid] && oi < sI[tid])) {
                    sV[tid] = ov; sI[tid] = oi;
                }
            }
            __syncthreads();
        }
        const float M    = sV[0];
        const int  istar = sI[0];

        // --- S = sum sign(M - p_trg): exact integers, any order ---
        float ps = 0.0f;
        for (int r = tid; r < NB; r += 128) {
            float d = M - g_ptrg[r];
            ps += (d > 0.0f) ? 1.0f : ((d < 0.0f) ? -1.0f : 0.0f);
        }
        sS[tid] = ps;
        __syncthreads();
#pragma unroll
        for (int off = 64; off; off >>= 1) {
            if (tid < off) sS[tid] += sS[tid + off];
            __syncthreads();
        }
        const float S     = sS[0];
        const int   jstar = g_jmax[pr][istar];
        const float bc1   = sBC[0];
        const float bc2   = sBC[1];

        // --- Phase B: row update from registers ---
        const float d1    = (lse - uy) - ltrg;
        const float sign1 = (d1 > 0.0f) ? 1.0f : ((d1 < 0.0f) ? -1.0f : 0.0f);
        const bool  isStar = (i == istar);
        const float c2 = BETA * S * M;

        float bvn = -INFINITY; int bjn = NC;
        float uyNew = 0.0f;

#pragma unroll
        for (int k = 0; k < 32; k++) {
            int j = k * 32 + lane;
            if (j < NC) {
                float s = expf(u[k] - lse);
                float g = sign1 * (s - ((j == y) ? 1.0f : 0.0f));
                if (isStar) g += c2 * (((j == jstar) ? 1.0f : 0.0f) - s);
                float m, v;
                if (t == 1) { m = 0.1f * g;                   v = 0.001f * g * g; }
                else        { m = 0.9f * mrow[j] + 0.1f * g;
                              v = 0.999f * vrow[j] + 0.001f * g * g; }
                mrow[j] = m; vrow[j] = v;
                float upd  = (m * bc1) / (sqrtf(v * bc2) + EPS_F);
                float unew = u[k] * DECAY - LR * upd;
                u[k] = unew;
                if (unew > bvn) { bvn = unew; bjn = j; }
                if (j == y) uyNew = unew;
            }
        }

#pragma unroll
        for (int off = 16; off; off >>= 1) {
            float ov = __shfl_down_sync(0xffffffffu, bvn, off);
            int   oj = __shfl_down_sync(0xffffffffu, bjn, off);
            if (ov > bvn || (ov == bvn && oj < bjn)) { bvn = ov; bjn = oj; }
        }
        bvn = __shfl_sync(0xffffffffu, bvn, 0);
        bjn = __shfl_sync(0xffffffffu, bjn, 0);

        float se2 = 0.0f;
#pragma unroll
        for (int k = 0; k < 32; k++) {
            int j = k * 32 + lane;
            if (j < NC) se2 += expf(u[k] - bvn);
        }
#pragma unroll
        for (int off = 16; off; off >>= 1) se2 += __shfl_xor_sync(0xffffffffu, se2, off);

        uyNew = __shfl_sync(0xffffffffu, uyNew, y & 31);

        lse = bvn + logf(se2);   // lane-uniform
        uy  = uyNew;
        if (lane == 0) {
            g_pmax[pr ^ 1][i] = 1.0f / se2;
            g_jmax[pr ^ 1][i] = bjn;
        }
    }

    // ---- final writeback ----
#pragma unroll
    for (int k = 0; k < 32; k++) {
        int j = k * 32 + lane;
        if (j < NC) Urow[j] = u[k];
    }
}

// =====================================================================
extern "C" void kernel_launch(void* const* d_in, const int* in_sizes, int n_in,
                              void* d_out, int out_size)
{
    const float* x = (const float*)d_in[0];   // [4096, 2048]
    const float* W = (const float*)d_in[1];   // [2048, 1000]
    const float* b = (const float*)d_in[2];   // [1000]
    float* U = (float*)d_out;                 // [4096, 1000]

    dim3 ggrid((NC + 127) / 128, NB / 128);   // (8, 32) = 256 blocks, 1 wave
    sgemm_bias<<<ggrid, 256>>>(x, W, b, U);

    persist_steps<<<NB / 4, 128>>>(U);        // 1024 blocks, co-resident
}

// round 4
// speedup vs baseline: 1.1890x; 1.0437x over previous
#include <cuda_runtime.h>
#include <math.h>

#define NB 4096
#define NC 1000
#define ND 2048

#define TAU   6.0f
#define ALPHA 1.0f
#define BETA  5.0f
#define LR    0.1f
#define PI_F  3.14159265358979f
#define EPS_F 1e-8f
#define DECAY 0.999f   /* 1 - LR*WD */

// ---- scratch state (device globals: no allocation allowed) ----
__device__ float2 g_mv[NB * NC];     // interleaved {m, v}
__device__ float  g_ptrg[NB];        // constant per row
__device__ float  g_psort[NB];       // sorted copy of g_ptrg
__device__ float2 g_bc[104];         // bias-correction table (bc1, bc2)

struct KeySlot { unsigned long long k; unsigned long long pad[15]; }; // 128B
__device__ KeySlot g_key[104];       // one cache line each; each read once

__device__ int           g_bar_count;
__device__ volatile int  g_bar_gen;

// key = [pmax_bits:32 | (4095-row):12 | jmax:12]  (pmax>0 so bits order-safe)
__device__ __forceinline__ unsigned long long make_key(float pm, int row, int jm)
{
    return (((unsigned long long)__float_as_uint(pm)) << 24)
         | (((unsigned long long)(4095 - row)) << 12)
         | (unsigned long long)jm;
}

// =====================================================================
// setup: zero keys, build bias-correction table (exact serial products)
// =====================================================================
__global__ void setup_kernel()
{
    int t = threadIdx.x;
    if (t < 104) g_key[t].k = 0ull;
    if (t >= 1 && t <= 100) {
        double p1 = 1.0, p2 = 1.0;
        for (int s = 0; s < t; s++) { p1 *= 0.9; p2 *= 0.999; }
        g_bc[t] = make_float2((float)(1.0 / (1.0 - p1)),
                              (float)(1.0 / (1.0 - p2)));
    }
}

// =====================================================================
// GEMM: z = x @ W + b. 64x64 tile, BK=16, 256 thr, 4x4/thr, double-buf.
// Per-output fmaf chain is k-sequential 0..2047.
// =====================================================================
__global__ __launch_bounds__(256) void sgemm_bias(
    const float* __restrict__ A,   // [NB, ND]
    const float* __restrict__ B,   // [ND, NC]
    const float* __restrict__ bias,// [NC]
    float* __restrict__ C)         // [NB, NC]
{
    __shared__ float As[2][16][64];
    __shared__ float Bs[2][16][64];

    const int tid = threadIdx.x;
    const int tx = tid & 15;       // 16 col-groups of 4
    const int ty = tid >> 4;       // 16 row-groups of 4
    const int rowBase = blockIdx.y * 64;
    const int colBase = blockIdx.x * 64;

    // loader coords
    const int ar = tid >> 2;            // 0..63
    const int ak = (tid & 3) << 2;      // 0,4,8,12
    const int bk = tid >> 4;            // 0..15
    const int bc = (tid & 15) << 2;     // 0..60
    const int bgc = colBase + bc;

    float acc[4][4];
#pragma unroll
    for (int q = 0; q < 4; q++)
#pragma unroll
        for (int p = 0; p < 4; p++) acc[q][p] = 0.0f;

    // prologue: tile 0
    {
        float4 av = *reinterpret_cast<const float4*>(
            &A[(size_t)(rowBase + ar) * ND + ak]);
        As[0][ak + 0][ar] = av.x;
        As[0][ak + 1][ar] = av.y;
        As[0][ak + 2][ar] = av.z;
        As[0][ak + 3][ar] = av.w;
        float4 bv = make_float4(0.f, 0.f, 0.f, 0.f);
        if (bgc < NC)
            bv = *reinterpret_cast<const float4*>(&B[(size_t)bk * NC + bgc]);
        *reinterpret_cast<float4*>(&Bs[0][bk][bc]) = bv;
    }
    __syncthreads();

    int buf = 0;
    for (int kt = 0; kt < ND / 16; kt++) {
        float4 pa, pb;
        const bool hasNext = (kt + 1 < ND / 16);
        if (hasNext) {
            int k0 = (kt + 1) * 16;
            pa = *reinterpret_cast<const float4*>(
                &A[(size_t)(rowBase + ar) * ND + k0 + ak]);
            pb = make_float4(0.f, 0.f, 0.f, 0.f);
            if (bgc < NC)
                pb = *reinterpret_cast<const float4*>(
                    &B[(size_t)(k0 + bk) * NC + bgc]);
        }

#pragma unroll
        for (int kk = 0; kk < 16; kk++) {
            float4 a4 = *reinterpret_cast<float4*>(&As[buf][kk][ty * 4]);
            float4 b4 = *reinterpret_cast<float4*>(&Bs[buf][kk][tx * 4]);
            float a[4] = {a4.x, a4.y, a4.z, a4.w};
            float bb[4] = {b4.x, b4.y, b4.z, b4.w};
#pragma unroll
            for (int q = 0; q < 4; q++)
#pragma unroll
                for (int p = 0; p < 4; p++)
                    acc[q][p] = fmaf(a[q], bb[p], acc[q][p]);
        }

        if (hasNext) {
            int nb = buf ^ 1;
            As[nb][ak + 0][ar] = pa.x;
            As[nb][ak + 1][ar] = pa.y;
            As[nb][ak + 2][ar] = pa.z;
            As[nb][ak + 3][ar] = pa.w;
            *reinterpret_cast<float4*>(&Bs[nb][bk][bc]) = pb;
            __syncthreads();
            buf = nb;
        }
    }

    const int cbase = colBase + tx * 4;
    if (cbase < NC) {
        float4 bv = *reinterpret_cast<const float4*>(&bias[cbase]);
#pragma unroll
        for (int q = 0; q < 4; q++) {
            int r = rowBase + ty * 4 + q;
            float4 o;
            o.x = acc[q][0] + bv.x;
            o.y = acc[q][1] + bv.y;
            o.z = acc[q][2] + bv.z;
            o.w = acc[q][3] + bv.w;
            *reinterpret_cast<float4*>(&C[(size_t)r * NC + cbase]) = o;
        }
    }
}

// =====================================================================
// software grid barrier (all 1024 blocks co-resident)
// =====================================================================
__device__ __forceinline__ void grid_barrier(int nblocks)
{
    __syncthreads();
    __threadfence();
    if (threadIdx.x == 0) {
        int gen = g_bar_gen;
        if (atomicAdd(&g_bar_count, 1) == nblocks - 1) {
            g_bar_count = 0;
            __threadfence();
            g_bar_gen = gen + 1;
        } else {
            while (g_bar_gen == gen) { __nanosleep(32); }
        }
    }
    __syncthreads();
    __threadfence();
}

// =====================================================================
// Persistent kernel: init stats + 100 AdamW steps. Warp-per-row, u in
// registers; m,v stream as float2 through L2. 1024 blocks x 128 thr.
// =====================================================================
__global__ __launch_bounds__(128, 7) void persist_steps(float* __restrict__ U)
{
    __shared__ float sSorted[NB];          // 16KB: sorted ptrg (per block)
    __shared__ unsigned long long sKey[4];

    const int tid  = threadIdx.x;
    const int lane = tid & 31;
    const int w    = tid >> 5;
    const int i    = blockIdx.x * 4 + w;
    const int nblocks = gridDim.x;

    float*  Urow  = U    + (size_t)i * NC;
    float2* mvrow = g_mv + (size_t)i * NC;

    // ---- load row into registers ----
    float u[32];
#pragma unroll
    for (int k = 0; k < 32; k++) {
        int j = k * 32 + lane;
        u[k] = (j < NC) ? Urow[j] : -INFINITY;
    }

    // ---- init stats (identical arithmetic to prior rounds) ----
    float bv = -INFINITY; int bj = NC;
#pragma unroll
    for (int k = 0; k < 32; k++) {
        int j = k * 32 + lane;
        if (j < NC) { if (u[k] > bv) { bv = u[k]; bj = j; } }
    }
#pragma unroll
    for (int off = 16; off; off >>= 1) {
        float ov = __shfl_down_sync(0xffffffffu, bv, off);
        int   oj = __shfl_down_sync(0xffffffffu, bj, off);
        if (ov > bv || (ov == bv && oj < bj)) { bv = ov; bj = oj; }
    }
    bv = __shfl_sync(0xffffffffu, bv, 0);
    bj = __shfl_sync(0xffffffffu, bj, 0);

    float se = 0.0f;
#pragma unroll
    for (int k = 0; k < 32; k++) {
        int j = k * 32 + lane;
        if (j < NC) se += expf(u[k] - bv);
    }
#pragma unroll
    for (int off = 16; off; off >>= 1) se += __shfl_xor_sync(0xffffffffu, se, off);

    float l_org = logf(se);
    float l_atr = (floorf(l_org / TAU) + 0.5f) * TAU;
    const float ltrg = l_org - ALPHA * TAU *
                       sinf(PI_F * (1.0f - 2.0f * (l_org - l_atr) / TAU));
    float pm  = 1.0f / se;
    float lse = bv + l_org;     // lane-uniform
    float uy  = bv;             // z[i, y] = rowmax
    const int y = bj;

    if (lane == 0) {
        g_ptrg[i] = pm;
        sKey[w]   = make_key(pm, i, bj);
    }
    __syncthreads();
    if (tid == 0) {
        unsigned long long kk = sKey[0];
#pragma unroll
        for (int q = 1; q < 4; q++) if (sKey[q] > kk) kk = sKey[q];
        atomicMax(&g_key[1].k, kk);
    }

    grid_barrier(nblocks);       // ptrg + key[1] globally visible

    // ---- block 0: bitonic sort ptrg -> g_psort (once) ----
    if (blockIdx.x == 0) {
        for (int q = tid; q < NB; q += 128) sSorted[q] = g_ptrg[q];
        __syncthreads();
        for (int kk = 2; kk <= NB; kk <<= 1) {
            for (int jj = kk >> 1; jj > 0; jj >>= 1) {
                for (int idx = tid; idx < NB; idx += 128) {
                    int ixj = idx ^ jj;
                    if (ixj > idx) {
                        bool up = ((idx & kk) == 0);
                        float a = sSorted[idx], c = sSorted[ixj];
                        if ((a > c) == up) { sSorted[idx] = c; sSorted[ixj] = a; }
                    }
                }
                __syncthreads();
            }
        }
        for (int q = tid; q < NB; q += 128) g_psort[q] = sSorted[q];
    }

    grid_barrier(nblocks);       // g_psort visible

    for (int q = tid; q < NB; q += 128) sSorted[q] = g_psort[q];
    __syncthreads();

    // =================== step loop ===================
    for (int t = 1; t <= 100; t++) {
        if (t > 1) grid_barrier(nblocks);

        // --- phase A: scalars from one key + smem binary searches ---
        const unsigned long long key = g_key[t].k;  // line read exactly once
        const float M     = __uint_as_float((unsigned int)(key >> 24));
        const int   istar = 4095 - (int)((key >> 12) & 0xFFF);
        const int   jstar = (int)(key & 0xFFF);
        const float2 bcv  = g_bc[t];

        int lo = 0, hi = NB;                    // lb: first >= M
        while (lo < hi) { int mid = (lo + hi) >> 1;
                          if (sSorted[mid] < M) lo = mid + 1; else hi = mid; }
        const int lb = lo;
        lo = 0; hi = NB;                        // ub: first > M
        while (lo < hi) { int mid = (lo + hi) >> 1;
                          if (sSorted[mid] <= M) lo = mid + 1; else hi = mid; }
        const float S = (float)(lb - (NB - lo));

        // --- phase B: row update (identical arithmetic) ---
        const float d1    = (lse - uy) - ltrg;
        const float sign1 = (d1 > 0.0f) ? 1.0f : ((d1 < 0.0f) ? -1.0f : 0.0f);
        const bool  isStar = (i == istar);
        const float c2 = BETA * S * M;
        const float bc1 = bcv.x, bc2 = bcv.y;

        float bvn = -INFINITY; int bjn = NC;
        float uyNew = 0.0f;

#pragma unroll
        for (int kg = 0; kg < 4; kg++) {
            float2 mv[8];
            if (t > 1) {
#pragma unroll
                for (int q = 0; q < 8; q++) {
                    int j = (kg * 8 + q) * 32 + lane;
                    if (j < NC) mv[q] = mvrow[j];
                }
            }
#pragma unroll
            for (int q = 0; q < 8; q++) {
                const int k = kg * 8 + q;
                const int j = k * 32 + lane;
                if (j < NC) {
                    float s = expf(u[k] - lse);
                    float g = sign1 * (s - ((j == y) ? 1.0f : 0.0f));
                    if (isStar) g += c2 * (((j == jstar) ? 1.0f : 0.0f) - s);
                    float m, v;
                    if (t == 1) { m = 0.1f * g;                    v = 0.001f * g * g; }
                    else        { m = 0.9f * mv[q].x + 0.1f * g;
                                  v = 0.999f * mv[q].y + 0.001f * g * g; }
                    mvrow[j] = make_float2(m, v);
                    float upd  = (m * bc1) / (sqrtf(v * bc2) + EPS_F);
                    float unew = u[k] * DECAY - LR * upd;
                    u[k] = unew;
                    if (unew > bvn) { bvn = unew; bjn = j; }
                    if (j == y) uyNew = unew;
                }
            }
        }

#pragma unroll
        for (int off = 16; off; off >>= 1) {
            float ov = __shfl_down_sync(0xffffffffu, bvn, off);
            int   oj = __shfl_down_sync(0xffffffffu, bjn, off);
            if (ov > bvn || (ov == bvn && oj < bjn)) { bvn = ov; bjn = oj; }
        }
        bvn = __shfl_sync(0xffffffffu, bvn, 0);
        bjn = __shfl_sync(0xffffffffu, bjn, 0);

        float se2 = 0.0f;
#pragma unroll
        for (int k = 0; k < 32; k++) {
            int j = k * 32 + lane;
            if (j < NC) se2 += expf(u[k] - bvn);
        }
#pragma unroll
        for (int off = 16; off; off >>= 1) se2 += __shfl_xor_sync(0xffffffffu, se2, off);

        uyNew = __shfl_sync(0xffffffffu, uyNew, y & 31);

        lse = bvn + logf(se2);   // lane-uniform
        uy  = uyNew;

        if (lane == 0) sKey[w] = make_key(1.0f / se2, i, bjn);
        __syncthreads();
        if (tid == 0) {
            unsigned long long kk = sKey[0];
#pragma unroll
            for (int q = 1; q < 4; q++) if (sKey[q] > kk) kk = sKey[q];
            atomicMax(&g_key[t + 1].k, kk);
        }
        // next grid_barrier (or loop exit) orders sKey reuse
    }

    // ---- final writeback ----
#pragma unroll
    for (int k = 0; k < 32; k++) {
        int j = k * 32 + lane;
        if (j < NC) Urow[j] = u[k];
    }
}

// =====================================================================
extern "C" void kernel_launch(void* const* d_in, const int* in_sizes, int n_in,
                              void* d_out, int out_size)
{
    const float* x = (const float*)d_in[0];   // [4096, 2048]
    const float* W = (const float*)d_in[1];   // [2048, 1000]
    const float* b = (const float*)d_in[2];   // [1000]
    float* U = (float*)d_out;                 // [4096, 1000]

    // defensively maximize smem carveout so 7 blocks/SM fit (co-residency)
    static int carveoutDone = 0;
    if (!carveoutDone) {
        cudaFuncSetAttribute(persist_steps,
                             cudaFuncAttributePreferredSharedMemoryCarveout, 100);
        carveoutDone = 1;
    }

    setup_kernel<<<1, 128>>>();

    dim3 ggrid((NC + 63) / 64, NB / 64);      // (16, 64) = 1024 blocks
    sgemm_bias<<<ggrid, 256>>>(x, W, b, U);

    persist_steps<<<NB / 4, 128>>>(U);        // 1024 blocks, co-resident
}

// round 5
// speedup vs baseline: 1.3502x; 1.1356x over previous
#include <cuda_runtime.h>
#include <math.h>

#define NB 4096
#define NC 1000
#define ND 2048
#define NBLK 1024

#define TAU   6.0f
#define ALPHA 1.0f
#define BETA  5.0f
#define LR    0.1f
#define PI_F  3.14159265358979f
#define EPS_F 1e-8f
#define DECAY 0.999f   /* 1 - LR*WD */

// ---- scratch state (device globals: no allocation allowed) ----
__device__ float2 g_mv[NB * NC];     // only used by fallback variant
__device__ float  g_ptrg[NB];        // constant per row

struct KeySlot { unsigned long long k; unsigned long long pad[15]; }; // 128B
__device__ KeySlot g_key[104];
struct CntSlot { int c; int pad[31]; };                               // 128B
__device__ CntSlot g_cnt[104];

// key = [pmax_bits:32 | (4095-row):12 | jmax:12]  (pmax>0 so bit order == value order)
__device__ __forceinline__ unsigned long long make_key(float pm, int row, int jm)
{
    return (((unsigned long long)__float_as_uint(pm)) << 24)
         | (((unsigned long long)(4095 - row)) << 12)
         | (unsigned long long)jm;
}

__device__ __forceinline__ void red_release_add1(int* p)
{
    asm volatile("red.release.gpu.global.add.s32 [%0], 1;" :: "l"(p) : "memory");
}
__device__ __forceinline__ int ld_acquire(const int* p)
{
    int v;
    asm volatile("ld.acquire.gpu.global.s32 %0, [%1];" : "=r"(v) : "l"(p) : "memory");
    return v;
}

// =====================================================================
// setup: zero key/counter slots (rerun every graph replay)
// =====================================================================
__global__ void setup_kernel()
{
    int t = threadIdx.x;
    if (t < 104) { g_key[t].k = 0ull; g_cnt[t].c = 0; }
}

// =====================================================================
// GEMM: z = x @ W + b. 64x64 tile, BK=16, 256 thr, 4x4/thr, double-buf.
// Per-output fmaf chain is k-sequential 0..2047 (bitwise stable).
// =====================================================================
__global__ __launch_bounds__(256) void sgemm_bias(
    const float* __restrict__ A, const float* __restrict__ B,
    const float* __restrict__ bias, float* __restrict__ C)
{
    __shared__ float As[2][16][64];
    __shared__ float Bs[2][16][64];

    const int tid = threadIdx.x;
    const int tx = tid & 15;
    const int ty = tid >> 4;
    const int rowBase = blockIdx.y * 64;
    const int colBase = blockIdx.x * 64;

    const int ar = tid >> 2;
    const int ak = (tid & 3) << 2;
    const int bk = tid >> 4;
    const int bc = (tid & 15) << 2;
    const int bgc = colBase + bc;

    float acc[4][4];
#pragma unroll
    for (int q = 0; q < 4; q++)
#pragma unroll
        for (int p = 0; p < 4; p++) acc[q][p] = 0.0f;

    {
        float4 av = *reinterpret_cast<const float4*>(
            &A[(size_t)(rowBase + ar) * ND + ak]);
        As[0][ak + 0][ar] = av.x; As[0][ak + 1][ar] = av.y;
        As[0][ak + 2][ar] = av.z; As[0][ak + 3][ar] = av.w;
        float4 bv = make_float4(0.f, 0.f, 0.f, 0.f);
        if (bgc < NC)
            bv = *reinterpret_cast<const float4*>(&B[(size_t)bk * NC + bgc]);
        *reinterpret_cast<float4*>(&Bs[0][bk][bc]) = bv;
    }
    __syncthreads();

    int buf = 0;
    for (int kt = 0; kt < ND / 16; kt++) {
        float4 pa, pb;
        const bool hasNext = (kt + 1 < ND / 16);
        if (hasNext) {
            int k0 = (kt + 1) * 16;
            pa = *reinterpret_cast<const float4*>(
                &A[(size_t)(rowBase + ar) * ND + k0 + ak]);
            pb = make_float4(0.f, 0.f, 0.f, 0.f);
            if (bgc < NC)
                pb = *reinterpret_cast<const float4*>(
                    &B[(size_t)(k0 + bk) * NC + bgc]);
        }

#pragma unroll
        for (int kk = 0; kk < 16; kk++) {
            float4 a4 = *reinterpret_cast<float4*>(&As[buf][kk][ty * 4]);
            float4 b4 = *reinterpret_cast<float4*>(&Bs[buf][kk][tx * 4]);
            float a[4] = {a4.x, a4.y, a4.z, a4.w};
            float bb[4] = {b4.x, b4.y, b4.z, b4.w};
#pragma unroll
            for (int q = 0; q < 4; q++)
#pragma unroll
                for (int p = 0; p < 4; p++)
                    acc[q][p] = fmaf(a[q], bb[p], acc[q][p]);
        }

        if (hasNext) {
            int nb = buf ^ 1;
            As[nb][ak + 0][ar] = pa.x; As[nb][ak + 1][ar] = pa.y;
            As[nb][ak + 2][ar] = pa.z; As[nb][ak + 3][ar] = pa.w;
            *reinterpret_cast<float4*>(&Bs[nb][bk][bc]) = pb;
            __syncthreads();
            buf = nb;
        }
    }

    const int cbase = colBase + tx * 4;
    if (cbase < NC) {
        float4 bv = *reinterpret_cast<const float4*>(&bias[cbase]);
#pragma unroll
        for (int q = 0; q < 4; q++) {
            int r = rowBase + ty * 4 + q;
            float4 o;
            o.x = acc[q][0] + bv.x; o.y = acc[q][1] + bv.y;
            o.z = acc[q][2] + bv.z; o.w = acc[q][3] + bv.w;
            *reinterpret_cast<float4*>(&C[(size_t)r * NC + cbase]) = o;
        }
    }
}

// =====================================================================
// Persistent kernel (template): init stats + 100 AdamW steps.
// Warp-per-row, u in registers. SMEMV: m,v in shared; else gmem (L2).
// 1024 blocks x 128 threads. Barrier: per-step counters, acq/rel.
// =====================================================================
template<bool SMEMV>
__global__ __launch_bounds__(128, 7) void persist_steps(float* __restrict__ U)
{
    __shared__ float2 smv[4][SMEMV ? NC : 1];
    __shared__ unsigned long long sKey[4];
    __shared__ float  sRed4[4];
    __shared__ float2 sBC;

    const int tid  = threadIdx.x;
    const int lane = tid & 31;
    const int w    = tid >> 5;
    const int i    = blockIdx.x * 4 + w;

    float*  Urow  = U + (size_t)i * NC;
    float2* mvrow = SMEMV ? &smv[w][0] : (g_mv + (size_t)i * NC);

    // ---- load row into registers ----
    float u[32];
#pragma unroll
    for (int k = 0; k < 32; k++) {
        int j = k * 32 + lane;
        u[k] = (j < NC) ? Urow[j] : -INFINITY;
    }

    // ---- init stats (identical arithmetic to prior rounds) ----
    float bv = -INFINITY; int bj = NC;
#pragma unroll
    for (int k = 0; k < 32; k++) {
        int j = k * 32 + lane;
        if (j < NC) { if (u[k] > bv) { bv = u[k]; bj = j; } }
    }
#pragma unroll
    for (int off = 16; off; off >>= 1) {
        float ov = __shfl_down_sync(0xffffffffu, bv, off);
        int   oj = __shfl_down_sync(0xffffffffu, bj, off);
        if (ov > bv || (ov == bv && oj < bj)) { bv = ov; bj = oj; }
    }
    bv = __shfl_sync(0xffffffffu, bv, 0);
    bj = __shfl_sync(0xffffffffu, bj, 0);

    float se = 0.0f;
#pragma unroll
    for (int k = 0; k < 32; k++) {
        int j = k * 32 + lane;
        if (j < NC) se += expf(u[k] - bv);
    }
#pragma unroll
    for (int off = 16; off; off >>= 1) se += __shfl_xor_sync(0xffffffffu, se, off);

    float l_org = logf(se);
    float l_atr = (floorf(l_org / TAU) + 0.5f) * TAU;
    const float ltrg = l_org - ALPHA * TAU *
                       sinf(PI_F * (1.0f - 2.0f * (l_org - l_atr) / TAU));
    float pm  = 1.0f / se;
    float lse = bv + l_org;     // lane-uniform
    float uy  = bv;             // z[i, y] = rowmax
    const int y = bj;

    if (lane == 0) {
        g_ptrg[i] = pm;
        sKey[w]   = make_key(pm, i, bj);
    }
    __syncthreads();
    if (tid == 0) {
        unsigned long long kk = sKey[0];
#pragma unroll
        for (int q = 1; q < 4; q++) if (sKey[q] > kk) kk = sKey[q];
        atomicMax(&g_key[1].k, kk);
        red_release_add1(&g_cnt[1].c);   // orders ptrg store + atomicMax
    }

    // bias-correction running products (tid 0 only; R2-proven bitwise)
    double p1 = 1.0, p2 = 1.0;

    // =================== step loop ===================
    for (int t = 1; t <= 100; t++) {
        // wait for key_t final
        if (tid == 0) {
            while (ld_acquire(&g_cnt[t].c) < NBLK) __nanosleep(40);
            p1 *= 0.9; p2 *= 0.999;
            sBC = make_float2((float)(1.0 / (1.0 - p1)),
                              (float)(1.0 / (1.0 - p2)));
        }
        __syncthreads();

        const unsigned long long key = g_key[t].k;
        const float M     = __uint_as_float((unsigned int)(key >> 24));
        const int   istar = 4095 - (int)((key >> 12) & 0xFFF);
        const int   jstar = (int)(key & 0xFFF);
        const float bc1 = sBC.x, bc2 = sBC.y;

        // --- S only needed by the star row's block ---
        const bool starBlk = ((istar >> 2) == (int)blockIdx.x);
        float S = 0.0f;
        if (starBlk) {
            float ps = 0.0f;
            for (int r = tid; r < NB; r += 128) {
                float d = M - g_ptrg[r];
                ps += (d > 0.0f) ? 1.0f : ((d < 0.0f) ? -1.0f : 0.0f);
            }
#pragma unroll
            for (int off = 16; off; off >>= 1)
                ps += __shfl_xor_sync(0xffffffffu, ps, off);
            if (lane == 0) sRed4[w] = ps;
            __syncthreads();
            S = sRed4[0] + sRed4[1] + sRed4[2] + sRed4[3];   // exact ints
        }

        // --- phase B: row update (identical arithmetic) ---
        const float d1    = (lse - uy) - ltrg;
        const float sign1 = (d1 > 0.0f) ? 1.0f : ((d1 < 0.0f) ? -1.0f : 0.0f);
        const bool  isStar = (i == istar);
        const float c2 = BETA * S * M;

        float bvn = -INFINITY; int bjn = NC;
        float uyNew = 0.0f;

#pragma unroll
        for (int kg = 0; kg < 4; kg++) {
            float2 mv[8];
            if (t > 1) {
#pragma unroll
                for (int q = 0; q < 8; q++) {
                    int j = (kg * 8 + q) * 32 + lane;
                    if (j < NC) mv[q] = mvrow[j];
                }
            }
#pragma unroll
            for (int q = 0; q < 8; q++) {
                const int k = kg * 8 + q;
                const int j = k * 32 + lane;
                if (j < NC) {
                    float s = expf(u[k] - lse);
                    float g = sign1 * (s - ((j == y) ? 1.0f : 0.0f));
                    if (isStar) g += c2 * (((j == jstar) ? 1.0f : 0.0f) - s);
                    float m, v;
                    if (t == 1) { m = 0.1f * g;                    v = 0.001f * g * g; }
                    else        { m = 0.9f * mv[q].x + 0.1f * g;
                                  v = 0.999f * mv[q].y + 0.001f * g * g; }
                    mvrow[j] = make_float2(m, v);
                    float upd  = (m * bc1) / (sqrtf(v * bc2) + EPS_F);
                    float unew = u[k] * DECAY - LR * upd;
                    u[k] = unew;
                    if (unew > bvn) { bvn = unew; bjn = j; }
                    if (j == y) uyNew = unew;
                }
            }
        }

#pragma unroll
        for (int off = 16; off; off >>= 1) {
            float ov = __shfl_down_sync(0xffffffffu, bvn, off);
            int   oj = __shfl_down_sync(0xffffffffu, bjn, off);
            if (ov > bvn || (ov == bvn && oj < bjn)) { bvn = ov; bjn = oj; }
        }
        bvn = __shfl_sync(0xffffffffu, bvn, 0);
        bjn = __shfl_sync(0xffffffffu, bjn, 0);

        float se2 = 0.0f;
#pragma unroll
        for (int k = 0; k < 32; k++) {
            int j = k * 32 + lane;
            if (j < NC) se2 += expf(u[k] - bvn);
        }
#pragma unroll
        for (int off = 16; off; off >>= 1) se2 += __shfl_xor_sync(0xffffffffu, se2, off);

        uyNew = __shfl_sync(0xffffffffu, uyNew, y & 31);

        lse = bvn + logf(se2);
        uy  = uyNew;

        if (t < 100) {
            if (lane == 0) sKey[w] = make_key(1.0f / se2, i, bjn);
            __syncthreads();
            if (tid == 0) {
                unsigned long long kk = sKey[0];
#pragma unroll
                for (int q = 1; q < 4; q++) if (sKey[q] > kk) kk = sKey[q];
                atomicMax(&g_key[t + 1].k, kk);
                red_release_add1(&g_cnt[t + 1].c);
            }
        }
    }

    // ---- final writeback ----
#pragma unroll
    for (int k = 0; k < 32; k++) {
        int j = k * 32 + lane;
        if (j < NC) Urow[j] = u[k];
    }
}

// =====================================================================
extern "C" void kernel_launch(void* const* d_in, const int* in_sizes, int n_in,
                              void* d_out, int out_size)
{
    const float* x = (const float*)d_in[0];
    const float* W = (const float*)d_in[1];
    const float* b = (const float*)d_in[2];
    float* U = (float*)d_out;

    // One-time: verify smem-m,v variant is fully co-resident (deadlock-proof).
    // Decided on the correctness run (pre-capture); deterministic thereafter.
    static int useSmem = -1;
    if (useSmem < 0) {
        cudaFuncSetAttribute(persist_steps<true>,
                             cudaFuncAttributePreferredSharedMemoryCarveout, 100);
        int occ = 0, sms = 0, dev = 0;
        cudaGetDevice(&dev);
        cudaDeviceGetAttribute(&sms, cudaDevAttrMultiProcessorCount, dev);
        cudaOccupancyMaxActiveBlocksPerMultiprocessor(
            &occ, persist_steps<true>, 128, 0);
        useSmem = (occ * sms >= NBLK) ? 1 : 0;
    }

    setup_kernel<<<1, 128>>>();

    dim3 ggrid((NC + 63) / 64, NB / 64);      // 1024 blocks
    sgemm_bias<<<ggrid, 256>>>(x, W, b, U);

    if (useSmem) persist_steps<true><<<NBLK, 128>>>(U);
    else         persist_steps<false><<<NBLK, 128>>>(U);
}